// round 1
// baseline (speedup 1.0000x reference)
#include <cuda_runtime.h>

// Problem constants (fixed by reference)
#define BATCH 16384
#define NN    1024
#define NI    128
#define NO    64
#define REFRACTORY 0.9f

// Tiling
#define KC    32     // K chunk
#define MT    64     // rows per CTA
#define NTHREADS 128 // tc in [0,16) x tr in [0,8); each thread: 8 rows x 4 cols

// Preprocessed weight slice: W_pre[k][j] = W[k][960+j] * (refractory if hidden k)
__device__ float g_Wpre[NN * NO];

__global__ void prep_kernel(const float* __restrict__ W) {
    int idx = blockIdx.x * blockDim.x + threadIdx.x;
    if (idx < NN * NO) {
        int k = idx / NO;
        int j = idx - k * NO;
        float f = (k >= NI && k < NN - NO) ? REFRACTORY : 1.0f;
        g_Wpre[idx] = W[(size_t)k * NN + (NN - NO) + j] * f;
    }
}

__device__ __forceinline__ unsigned long long pack2(float lo, float hi) {
    unsigned long long r;
    asm("mov.b64 %0, {%1, %2};" : "=l"(r) : "f"(lo), "f"(hi));
    return r;
}
__device__ __forceinline__ void unpack2(unsigned long long v, float& lo, float& hi) {
    asm("mov.b64 {%0, %1}, %2;" : "=f"(lo), "=f"(hi) : "l"(v));
}
__device__ __forceinline__ unsigned long long fma2(unsigned long long a,
                                                   unsigned long long b,
                                                   unsigned long long c) {
    unsigned long long d;
    asm("fma.rn.f32x2 %0, %1, %2, %3;" : "=l"(d) : "l"(a), "l"(b), "l"(c));
    return d;
}

__device__ __forceinline__ float activate(float x, int a) {
    if (a == 0) return fmaxf(x, 0.0f);
    if (a == 1) return tanhf(x);
    if (a == 2) return 1.0f / (1.0f + expf(-x));
    return x;
}

__global__ void __launch_bounds__(NTHREADS)
nn_gemm_kernel(const float* __restrict__ prev,    // [B, N]
               const float* __restrict__ inp,     // [B, I]
               const float* __restrict__ biases,  // [N]
               const int*   __restrict__ act,     // [N]
               float* __restrict__ out)           // [B, O]
{
    // States tile transposed: s_s[kk][row], padded so row stride = 66 floats
    // (264 B: 8B-aligned for LDS.64 row-pair loads; STS 2-way conflict only).
    __shared__ __align__(16) float s_s[KC][MT + 2];
    __shared__ __align__(16) float s_w[KC][NO];

    const int tid = threadIdx.x;
    const int tc  = tid & 15;   // column group (4 cols)
    const int tr  = tid >> 4;   // row group (8 rows)
    const int row0 = blockIdx.x * MT;

    // Per-thread output columns: tc*4 .. tc*4+3  (global col 960 + ...)
    float bias_c[4];
    int   act_c[4];
#pragma unroll
    for (int c = 0; c < 4; ++c) {
        int col = tc * 4 + c;
        bias_c[c] = biases[NN - NO + col];
        act_c[c]  = act[NN - NO + col];
    }

    // Accumulators: row-pairs (f32x2 = {even row, odd row}) x 4 cols
    unsigned long long acc[4][4];
#pragma unroll
    for (int rp = 0; rp < 4; ++rp)
#pragma unroll
        for (int c = 0; c < 4; ++c) acc[rp][c] = 0ull;

    const int lane  = tid & 31;  // kk for state loads
    const int rbase = tid >> 5;  // 0..3

    for (int kc = 0; kc < NN / KC; ++kc) {
        const int k0 = kc * KC;

        // ---- load states tile (transposed) ----
        // chunk is entirely input (k<128) or entirely prev (k>=128): KC | NI
        {
            const float* src = (k0 < NI) ? inp : prev;
            const int ld     = (k0 < NI) ? NI : NN;
            const int kg     = k0 + lane;
#pragma unroll
            for (int r = 0; r < MT / 4; ++r) {
                int row = rbase + r * 4;
                s_s[lane][row] = src[(size_t)(row0 + row) * ld + kg];
            }
        }
        // ---- load W tile ----
        {
            const float4* wsrc = (const float4*)(g_Wpre + k0 * NO);
#pragma unroll
            for (int t = 0; t < 4; ++t) {
                int idx4 = tid + t * NTHREADS;      // 0..511
                int kk = idx4 >> 4, c4 = idx4 & 15;
                *(float4*)&s_w[kk][c4 * 4] = wsrc[idx4];
            }
        }
        __syncthreads();

        // ---- compute ----
#pragma unroll 8
        for (int k = 0; k < KC; ++k) {
            float4 wv = *(const float4*)&s_w[k][tc * 4];
            unsigned long long w0 = pack2(wv.x, wv.x);
            unsigned long long w1 = pack2(wv.y, wv.y);
            unsigned long long w2 = pack2(wv.z, wv.z);
            unsigned long long w3 = pack2(wv.w, wv.w);

            const float* sp = &s_s[k][tr * 8];
            unsigned long long s0 = *(const unsigned long long*)(sp + 0);
            unsigned long long s1 = *(const unsigned long long*)(sp + 2);
            unsigned long long s2 = *(const unsigned long long*)(sp + 4);
            unsigned long long s3 = *(const unsigned long long*)(sp + 6);

            acc[0][0] = fma2(s0, w0, acc[0][0]);
            acc[0][1] = fma2(s0, w1, acc[0][1]);
            acc[0][2] = fma2(s0, w2, acc[0][2]);
            acc[0][3] = fma2(s0, w3, acc[0][3]);
            acc[1][0] = fma2(s1, w0, acc[1][0]);
            acc[1][1] = fma2(s1, w1, acc[1][1]);
            acc[1][2] = fma2(s1, w2, acc[1][2]);
            acc[1][3] = fma2(s1, w3, acc[1][3]);
            acc[2][0] = fma2(s2, w0, acc[2][0]);
            acc[2][1] = fma2(s2, w1, acc[2][1]);
            acc[2][2] = fma2(s2, w2, acc[2][2]);
            acc[2][3] = fma2(s2, w3, acc[2][3]);
            acc[3][0] = fma2(s3, w0, acc[3][0]);
            acc[3][1] = fma2(s3, w1, acc[3][1]);
            acc[3][2] = fma2(s3, w2, acc[3][2]);
            acc[3][3] = fma2(s3, w3, acc[3][3]);
        }
        __syncthreads();
    }

    // ---- epilogue: bias + heterogeneous activation + store ----
#pragma unroll
    for (int rp = 0; rp < 4; ++rp) {
        float v0[4], v1[4];
#pragma unroll
        for (int c = 0; c < 4; ++c) unpack2(acc[rp][c], v0[c], v1[c]);

        int row_e = row0 + tr * 8 + rp * 2;
        float4 oe, oo;
        oe.x = activate(v0[0] + bias_c[0], act_c[0]);
        oe.y = activate(v0[1] + bias_c[1], act_c[1]);
        oe.z = activate(v0[2] + bias_c[2], act_c[2]);
        oe.w = activate(v0[3] + bias_c[3], act_c[3]);
        oo.x = activate(v1[0] + bias_c[0], act_c[0]);
        oo.y = activate(v1[1] + bias_c[1], act_c[1]);
        oo.z = activate(v1[2] + bias_c[2], act_c[2]);
        oo.w = activate(v1[3] + bias_c[3], act_c[3]);
        *(float4*)&out[(size_t)row_e * NO + tc * 4]       = oe;
        *(float4*)&out[(size_t)(row_e + 1) * NO + tc * 4] = oo;
    }
}

extern "C" void kernel_launch(void* const* d_in, const int* in_sizes, int n_in,
                              void* d_out, int out_size) {
    const float* prev   = (const float*)d_in[0];  // [16384,1024]
    const float* inp    = (const float*)d_in[1];  // [16384,128]
    const float* W      = (const float*)d_in[2];  // [1024,1024]
    const float* biases = (const float*)d_in[3];  // [1024]
    const int*   act    = (const int*)d_in[4];    // [1024]
    float* out = (float*)d_out;                   // [16384,64]

    prep_kernel<<<(NN * NO + 255) / 256, 256>>>(W);
    nn_gemm_kernel<<<BATCH / MT, NTHREADS>>>(prev, inp, biases, act, out);
}

// round 3
// speedup vs baseline: 2.0936x; 2.0936x over previous
#include <cuda_runtime.h>
#include <cuda_bf16.h>
#include <cstdint>

// Problem constants
#define BATCH 16384
#define NN    1024
#define NI    128
#define NO    64
#define REFRACTORY 0.9f

// Tiling
#define MT       128            // batch rows per CTA
#define KC       64             // k per chunk
#define NCHUNK   (NN / KC)      // 16
#define NTHREADS 256            // 8 warps: 4 m-groups x 2 n-groups

// ---- dynamic smem layout ----
// [0,256)   bias[64] f32     [256,512) act[64] i32
// [1024+)   double buffer, 48KB each:
//           AH 16KB | AL 16KB | BH 8KB | BL 8KB
#define SMEM_BIAS  0
#define SMEM_ACT   256
#define SMEM_BUF0  1024
#define AH_OFF     0
#define AL_OFF     16384
#define BH_OFF     32768
#define BL_OFF     40960
#define BUF_STRIDE 49152
#define SMEM_TOTAL (SMEM_BUF0 + 2 * BUF_STRIDE)   // 99328

// Pre-swizzled, hi/lo-split, refractory-folded weight images.
// g_Bimg[chunk][0=hi,1=lo]: exact smem tile image, [kl 0..63][n 0..63] bf16,
// 128B rows, SW128 swizzled.
__device__ __align__(16) unsigned char g_Bimg[NCHUNK][2][NO * 128];

__device__ __forceinline__ uint32_t sw128(uint32_t off) { return off ^ ((off >> 3) & 0x70); }

__device__ __forceinline__ uint32_t smem_u32(const void* p) {
    uint32_t a;
    asm("{ .reg .u64 t; cvta.to.shared.u64 t, %1; cvt.u32.u64 %0, t; }" : "=r"(a) : "l"(p));
    return a;
}

__device__ __forceinline__ void ldm_x4(uint32_t* r, uint32_t addr) {
    asm volatile("ldmatrix.sync.aligned.m8n8.x4.shared.b16 {%0,%1,%2,%3}, [%4];"
                 : "=r"(r[0]), "=r"(r[1]), "=r"(r[2]), "=r"(r[3]) : "r"(addr));
}
__device__ __forceinline__ void ldm_x4_t(uint32_t* r, uint32_t addr) {
    asm volatile("ldmatrix.sync.aligned.m8n8.x4.trans.shared.b16 {%0,%1,%2,%3}, [%4];"
                 : "=r"(r[0]), "=r"(r[1]), "=r"(r[2]), "=r"(r[3]) : "r"(addr));
}
__device__ __forceinline__ void mma_bf16(float* d, const uint32_t* a, uint32_t b0, uint32_t b1) {
    asm volatile(
        "mma.sync.aligned.m16n8k16.row.col.f32.bf16.bf16.f32 "
        "{%0,%1,%2,%3}, {%4,%5,%6,%7}, {%8,%9}, {%0,%1,%2,%3};"
        : "+f"(d[0]), "+f"(d[1]), "+f"(d[2]), "+f"(d[3])
        : "r"(a[0]), "r"(a[1]), "r"(a[2]), "r"(a[3]), "r"(b0), "r"(b1));
}
__device__ __forceinline__ void cp_async16(uint32_t smem_addr, const void* gptr) {
    asm volatile("cp.async.cg.shared.global [%0], [%1], 16;"
                 :: "r"(smem_addr), "l"(gptr) : "memory");
}
#define CP_COMMIT() asm volatile("cp.async.commit_group;" ::: "memory")
#define CP_WAIT0()  asm volatile("cp.async.wait_group 0;" ::: "memory")

// ---------------- prep: split + fold + pre-swizzle weight slice ----------------
__global__ void prep_kernel(const float* __restrict__ W) {
    int idx = blockIdx.x * blockDim.x + threadIdx.x;   // 0..NN*NO-1
    if (idx >= NN * NO) return;
    int k = idx >> 6;          // 0..1023
    int n = idx & 63;
    float f = (k >= NI && k < NN - NO) ? REFRACTORY : 1.0f;
    float v = W[(size_t)k * NN + (NN - NO) + n] * f;
    __nv_bfloat16 h = __float2bfloat16(v);
    __nv_bfloat16 l = __float2bfloat16(v - __bfloat162float(h));
    int chunk = k >> 6, kl = k & 63;
    uint32_t off = sw128((uint32_t)(kl * 128 + n * 2));
    *(__nv_bfloat16*)(g_Bimg[chunk][0] + off) = h;
    *(__nv_bfloat16*)(g_Bimg[chunk][1] + off) = l;
}

// ---------------- activation ----------------
__device__ __forceinline__ float activate(float x, int a) {
    if (a == 0) return fmaxf(x, 0.0f);
    if (a == 1) { float r; asm("tanh.approx.f32 %0, %1;" : "=f"(r) : "f"(x)); return r; }
    if (a == 2) {
        float e, r;
        asm("ex2.approx.f32 %0, %1;" : "=f"(e) : "f"(-1.4426950408889634f * x));
        asm("rcp.approx.f32 %0, %1;" : "=f"(r) : "f"(1.0f + e));
        return r;
    }
    return x;
}

// ---------------- main kernel ----------------
__global__ void __launch_bounds__(NTHREADS, 1)
nn_mma_kernel(const float* __restrict__ prev,    // [B, N]
              const float* __restrict__ inp,     // [B, I]
              const float* __restrict__ biases,  // [N]
              const int*   __restrict__ act,     // [N]
              float* __restrict__ out)           // [B, O]
{
    extern __shared__ unsigned char smem[];
    const uint32_t sb = smem_u32(smem);
    const int tid   = threadIdx.x;
    const int lane  = tid & 31;
    const int wid   = tid >> 5;
    const int warpm = wid >> 1;   // 0..3  (32 rows each)
    const int warpn = wid & 1;    // 0..1  (32 cols each)
    const int row0  = blockIdx.x * MT;

    float* sbias = (float*)(smem + SMEM_BIAS);
    int*   sact  = (int*)(smem + SMEM_ACT);
    if (tid < NO) {
        sbias[tid] = biases[NN - NO + tid];
        sact[tid]  = act[NN - NO + tid];
    }

    float acc[2][4][4];
#pragma unroll
    for (int mt = 0; mt < 2; ++mt)
#pragma unroll
        for (int nf = 0; nf < 4; ++nf)
#pragma unroll
            for (int i = 0; i < 4; ++i) acc[mt][nf][i] = 0.0f;

    float4 va[8];

    // ---- prologue: chunk 0 ----
    {
        const float* src = inp + (size_t)row0 * NI;   // chunk 0 is input cols 0..63
#pragma unroll
        for (int i = 0; i < 8; ++i) {
            int idx = tid + i * NTHREADS;
            int r = idx >> 4, f4 = idx & 15;
            va[i] = *(const float4*)(src + (size_t)r * NI + f4 * 4);
        }
        uint32_t dsth = sb + SMEM_BUF0 + BH_OFF;
        uint32_t dstl = sb + SMEM_BUF0 + BL_OFF;
        const unsigned char* gh = g_Bimg[0][0];
        const unsigned char* gl = g_Bimg[0][1];
        cp_async16(dsth + tid * 16, gh + tid * 16);
        cp_async16(dsth + (tid + 256) * 16, gh + (tid + 256) * 16);
        cp_async16(dstl + tid * 16, gl + tid * 16);
        cp_async16(dstl + (tid + 256) * 16, gl + (tid + 256) * 16);
        CP_COMMIT();

        unsigned char* bufp = smem + SMEM_BUF0;
#pragma unroll
        for (int i = 0; i < 8; ++i) {
            int idx = tid + i * NTHREADS;
            int r = idx >> 4, f4 = idx & 15;
            float4 v = va[i];
            __nv_bfloat162 h01 = __float22bfloat162_rn(make_float2(v.x, v.y));
            __nv_bfloat162 h23 = __float22bfloat162_rn(make_float2(v.z, v.w));
            float2 hf01 = __bfloat1622float2(h01);
            float2 hf23 = __bfloat1622float2(h23);
            __nv_bfloat162 l01 = __float22bfloat162_rn(make_float2(v.x - hf01.x, v.y - hf01.y));
            __nv_bfloat162 l23 = __float22bfloat162_rn(make_float2(v.z - hf23.x, v.w - hf23.y));
            uint32_t off = sw128((uint32_t)(r * 128 + f4 * 8));
            uint2 hh, ll;
            hh.x = *(uint32_t*)&h01; hh.y = *(uint32_t*)&h23;
            ll.x = *(uint32_t*)&l01; ll.y = *(uint32_t*)&l23;
            *(uint2*)(bufp + AH_OFF + off) = hh;
            *(uint2*)(bufp + AL_OFF + off) = ll;
        }
        CP_WAIT0();
        __syncthreads();
    }

    // ---- main loop ----
    for (int c = 0; c < NCHUNK; ++c) {
        const int p = c & 1;
        const uint32_t buf = sb + SMEM_BUF0 + p * BUF_STRIDE;

        // issue loads for chunk c+1 (A -> regs, B -> other buffer via cp.async)
        if (c + 1 < NCHUNK) {
            const int cc = c + 1;
            const float* src;
            int ldx;
            if (cc < 2) { src = inp  + (size_t)row0 * NI + cc * KC; ldx = NI; }
            else        { src = prev + (size_t)row0 * NN + cc * KC; ldx = NN; }
#pragma unroll
            for (int i = 0; i < 8; ++i) {
                int idx = tid + i * NTHREADS;
                int r = idx >> 4, f4 = idx & 15;
                va[i] = *(const float4*)(src + (size_t)r * ldx + f4 * 4);
            }
            uint32_t dsth = sb + SMEM_BUF0 + (p ^ 1) * BUF_STRIDE + BH_OFF;
            uint32_t dstl = sb + SMEM_BUF0 + (p ^ 1) * BUF_STRIDE + BL_OFF;
            const unsigned char* gh = g_Bimg[cc][0];
            const unsigned char* gl = g_Bimg[cc][1];
            cp_async16(dsth + tid * 16, gh + tid * 16);
            cp_async16(dsth + (tid + 256) * 16, gh + (tid + 256) * 16);
            cp_async16(dstl + tid * 16, gl + tid * 16);
            cp_async16(dstl + (tid + 256) * 16, gl + (tid + 256) * 16);
            CP_COMMIT();
        }

        // compute chunk c from buffer p
#pragma unroll
        for (int ks = 0; ks < 4; ++ks) {
            uint32_t ah[2][4], alr[2][4];
#pragma unroll
            for (int mt = 0; mt < 2; ++mt) {
                int row = warpm * 32 + mt * 16 + (lane & 15);
                int kc2 = ks * 16 + (lane >> 4) * 8;
                uint32_t off = sw128((uint32_t)(row * 128 + kc2 * 2));
                ldm_x4(ah[mt],  buf + AH_OFF + off);
                ldm_x4(alr[mt], buf + AL_OFF + off);
            }
            uint32_t bh[2][4], blr[2][4];
#pragma unroll
            for (int nb = 0; nb < 2; ++nb) {
                int kr = ks * 16 + (lane & 15);
                int nc = warpn * 32 + nb * 16 + (lane >> 4) * 8;
                uint32_t off = sw128((uint32_t)(kr * 128 + nc * 2));
                ldm_x4_t(bh[nb],  buf + BH_OFF + off);
                ldm_x4_t(blr[nb], buf + BL_OFF + off);
            }
#pragma unroll
            for (int mt = 0; mt < 2; ++mt)
#pragma unroll
                for (int nf = 0; nf < 4; ++nf) {
                    int nb = nf >> 1, s = (nf & 1) * 2;
                    mma_bf16(acc[mt][nf], ah[mt],  bh[nb][s],  bh[nb][s + 1]);
                    mma_bf16(acc[mt][nf], ah[mt],  blr[nb][s], blr[nb][s + 1]);
                    mma_bf16(acc[mt][nf], alr[mt], bh[nb][s],  bh[nb][s + 1]);
                }
        }

        // store chunk c+1's A into the other buffer, wait B, sync
        if (c + 1 < NCHUNK) {
            unsigned char* bufp = smem + SMEM_BUF0 + (p ^ 1) * BUF_STRIDE;
#pragma unroll
            for (int i = 0; i < 8; ++i) {
                int idx = tid + i * NTHREADS;
                int r = idx >> 4, f4 = idx & 15;
                float4 v = va[i];
                __nv_bfloat162 h01 = __float22bfloat162_rn(make_float2(v.x, v.y));
                __nv_bfloat162 h23 = __float22bfloat162_rn(make_float2(v.z, v.w));
                float2 hf01 = __bfloat1622float2(h01);
                float2 hf23 = __bfloat1622float2(h23);
                __nv_bfloat162 l01 = __float22bfloat162_rn(make_float2(v.x - hf01.x, v.y - hf01.y));
                __nv_bfloat162 l23 = __float22bfloat162_rn(make_float2(v.z - hf23.x, v.w - hf23.y));
                uint32_t off = sw128((uint32_t)(r * 128 + f4 * 8));
                uint2 hh, ll;
                hh.x = *(uint32_t*)&h01; hh.y = *(uint32_t*)&h23;
                ll.x = *(uint32_t*)&l01; ll.y = *(uint32_t*)&l23;
                *(uint2*)(bufp + AH_OFF + off) = hh;
                *(uint2*)(bufp + AL_OFF + off) = ll;
            }
            CP_WAIT0();
        }
        __syncthreads();
    }

    // ---- epilogue: bias + heterogeneous activation + store ----
#pragma unroll
    for (int mt = 0; mt < 2; ++mt)
#pragma unroll
        for (int nf = 0; nf < 4; ++nf) {
            int col = warpn * 32 + nf * 8 + (lane & 3) * 2;
            int rg  = row0 + warpm * 32 + mt * 16 + (lane >> 2);
            float b0 = sbias[col], b1 = sbias[col + 1];
            int   a0 = sact[col],  a1 = sact[col + 1];
            float2 o;
            o.x = activate(acc[mt][nf][0] + b0, a0);
            o.y = activate(acc[mt][nf][1] + b1, a1);
            *(float2*)(out + (size_t)rg * NO + col) = o;
            o.x = activate(acc[mt][nf][2] + b0, a0);
            o.y = activate(acc[mt][nf][3] + b1, a1);
            *(float2*)(out + (size_t)(rg + 8) * NO + col) = o;
        }
}

extern "C" void kernel_launch(void* const* d_in, const int* in_sizes, int n_in,
                              void* d_out, int out_size) {
    (void)in_sizes; (void)n_in; (void)out_size;
    const float* prev   = (const float*)d_in[0];  // [16384,1024]
    const float* inp    = (const float*)d_in[1];  // [16384,128]
    const float* W      = (const float*)d_in[2];  // [1024,1024]
    const float* biases = (const float*)d_in[3];  // [1024]
    const int*   act    = (const int*)d_in[4];    // [1024]
    float* out = (float*)d_out;                   // [16384,64]

    cudaFuncSetAttribute(nn_mma_kernel, cudaFuncAttributeMaxDynamicSharedMemorySize, SMEM_TOTAL);

    prep_kernel<<<(NN * NO + 255) / 256, 256>>>(W);
    nn_mma_kernel<<<BATCH / MT, NTHREADS, SMEM_TOTAL>>>(prev, inp, biases, act, out);
}

// round 4
// speedup vs baseline: 2.2276x; 1.0640x over previous
#include <cuda_runtime.h>
#include <cuda_bf16.h>
#include <cstdint>

// Problem constants
#define BATCH 16384
#define NN    1024
#define NI    128
#define NO    64
#define REFRACTORY 0.9f

// Tiling
#define MT       64             // batch rows per CTA
#define KC       64             // k per chunk
#define NCHUNK   (NN / KC)      // 16
#define NTHREADS 256            // 8 warps: 2 m-groups x 4 n-groups

// ---- dynamic smem layout ----
// [0,256)   bias[64] f32     [256,512) act[64] i32
// [1024+)   double buffer, 32KB each: AH 8K | AL 8K | BH 8K | BL 8K
#define SMEM_BIAS  0
#define SMEM_ACT   256
#define SMEM_BUF0  1024
#define AH_OFF     0
#define AL_OFF     8192
#define BH_OFF     16384
#define BL_OFF     24576
#define BUF_STRIDE 32768
#define SMEM_TOTAL (SMEM_BUF0 + 2 * BUF_STRIDE)   // 66560

// Pre-swizzled, hi/lo-split, refractory-folded weight images.
// g_Bimg[chunk][0=hi,1=lo]: [kl 0..63][n 0..63] bf16, 128B rows, SW128.
__device__ __align__(16) unsigned char g_Bimg[NCHUNK][2][NO * 128];

__device__ __forceinline__ uint32_t sw128(uint32_t off) { return off ^ ((off >> 3) & 0x70); }

__device__ __forceinline__ uint32_t smem_u32(const void* p) {
    uint32_t a;
    asm("{ .reg .u64 t; cvta.to.shared.u64 t, %1; cvt.u32.u64 %0, t; }" : "=r"(a) : "l"(p));
    return a;
}

__device__ __forceinline__ void ldm_x4(uint32_t* r, uint32_t addr) {
    asm volatile("ldmatrix.sync.aligned.m8n8.x4.shared.b16 {%0,%1,%2,%3}, [%4];"
                 : "=r"(r[0]), "=r"(r[1]), "=r"(r[2]), "=r"(r[3]) : "r"(addr));
}
__device__ __forceinline__ void ldm_x4_t(uint32_t* r, uint32_t addr) {
    asm volatile("ldmatrix.sync.aligned.m8n8.x4.trans.shared.b16 {%0,%1,%2,%3}, [%4];"
                 : "=r"(r[0]), "=r"(r[1]), "=r"(r[2]), "=r"(r[3]) : "r"(addr));
}
__device__ __forceinline__ void mma_bf16(float* d, const uint32_t* a, uint32_t b0, uint32_t b1) {
    asm volatile(
        "mma.sync.aligned.m16n8k16.row.col.f32.bf16.bf16.f32 "
        "{%0,%1,%2,%3}, {%4,%5,%6,%7}, {%8,%9}, {%0,%1,%2,%3};"
        : "+f"(d[0]), "+f"(d[1]), "+f"(d[2]), "+f"(d[3])
        : "r"(a[0]), "r"(a[1]), "r"(a[2]), "r"(a[3]), "r"(b0), "r"(b1));
}
__device__ __forceinline__ void cp_async16(uint32_t smem_addr, const void* gptr) {
    asm volatile("cp.async.cg.shared.global [%0], [%1], 16;"
                 :: "r"(smem_addr), "l"(gptr) : "memory");
}
#define CP_COMMIT() asm volatile("cp.async.commit_group;" ::: "memory")
#define CP_WAIT0()  asm volatile("cp.async.wait_group 0;" ::: "memory")

// ---------------- prep: split + fold + pre-swizzle weight slice ----------------
__global__ void prep_kernel(const float* __restrict__ W) {
    int idx = blockIdx.x * blockDim.x + threadIdx.x;   // 0..NN*NO-1
    if (idx >= NN * NO) return;
    int k = idx >> 6;          // 0..1023
    int n = idx & 63;
    float f = (k >= NI && k < NN - NO) ? REFRACTORY : 1.0f;
    float v = W[(size_t)k * NN + (NN - NO) + n] * f;
    __nv_bfloat16 h = __float2bfloat16(v);
    __nv_bfloat16 l = __float2bfloat16(v - __bfloat162float(h));
    int chunk = k >> 6, kl = k & 63;
    uint32_t off = sw128((uint32_t)(kl * 128 + n * 2));
    *(__nv_bfloat16*)(g_Bimg[chunk][0] + off) = h;
    *(__nv_bfloat16*)(g_Bimg[chunk][1] + off) = l;
}

// ---------------- activation ----------------
__device__ __forceinline__ float activate(float x, int a) {
    if (a == 0) return fmaxf(x, 0.0f);
    if (a == 1) { float r; asm("tanh.approx.f32 %0, %1;" : "=f"(r) : "f"(x)); return r; }
    if (a == 2) {
        float e, r;
        asm("ex2.approx.f32 %0, %1;" : "=f"(e) : "f"(-1.4426950408889634f * x));
        asm("rcp.approx.f32 %0, %1;" : "=f"(r) : "f"(1.0f + e));
        return r;
    }
    return x;
}

// convert 4 fp32 -> hi/lo bf16x2 pairs and store to swizzled A tiles
__device__ __forceinline__ void store_a_split(unsigned char* bufp, int r, int f4, float4 v) {
    __nv_bfloat162 h01 = __float22bfloat162_rn(make_float2(v.x, v.y));
    __nv_bfloat162 h23 = __float22bfloat162_rn(make_float2(v.z, v.w));
    float2 hf01 = __bfloat1622float2(h01);
    float2 hf23 = __bfloat1622float2(h23);
    __nv_bfloat162 l01 = __float22bfloat162_rn(make_float2(v.x - hf01.x, v.y - hf01.y));
    __nv_bfloat162 l23 = __float22bfloat162_rn(make_float2(v.z - hf23.x, v.w - hf23.y));
    uint32_t off = sw128((uint32_t)(r * 128 + f4 * 8));
    uint2 hh, ll;
    hh.x = *(uint32_t*)&h01; hh.y = *(uint32_t*)&h23;
    ll.x = *(uint32_t*)&l01; ll.y = *(uint32_t*)&l23;
    *(uint2*)(bufp + AH_OFF + off) = hh;
    *(uint2*)(bufp + AL_OFF + off) = ll;
}

// ---------------- main kernel ----------------
__global__ void __launch_bounds__(NTHREADS, 2)
nn_mma_kernel(const float* __restrict__ prev,    // [B, N]
              const float* __restrict__ inp,     // [B, I]
              const float* __restrict__ biases,  // [N]
              const int*   __restrict__ act,     // [N]
              float* __restrict__ out)           // [B, O]
{
    extern __shared__ unsigned char smem[];
    const uint32_t sb = smem_u32(smem);
    const int tid   = threadIdx.x;
    const int lane  = tid & 31;
    const int wid   = tid >> 5;
    const int warpm = wid >> 2;   // 0..1  (32 rows each)
    const int warpn = wid & 3;    // 0..3  (16 cols each)
    const int row0  = blockIdx.x * MT;

    float* sbias = (float*)(smem + SMEM_BIAS);
    int*   sact  = (int*)(smem + SMEM_ACT);
    if (tid < NO) {
        sbias[tid] = biases[NN - NO + tid];
        sact[tid]  = act[NN - NO + tid];
    }

    float acc[2][2][4];
#pragma unroll
    for (int mt = 0; mt < 2; ++mt)
#pragma unroll
        for (int nf = 0; nf < 2; ++nf)
#pragma unroll
            for (int i = 0; i < 4; ++i) acc[mt][nf][i] = 0.0f;

    float4 va[4];

    // ---- prologue: chunk 0 (input cols 0..63) ----
    {
        const float* src = inp + (size_t)row0 * NI;
#pragma unroll
        for (int i = 0; i < 4; ++i) {
            int idx = tid + i * NTHREADS;       // 0..1023
            int r = idx >> 4, f4 = idx & 15;    // 64 rows x 16 float4
            va[i] = *(const float4*)(src + (size_t)r * NI + f4 * 4);
        }
        uint32_t dsth = sb + SMEM_BUF0 + BH_OFF;
        uint32_t dstl = sb + SMEM_BUF0 + BL_OFF;
        const unsigned char* gh = g_Bimg[0][0];
        const unsigned char* gl = g_Bimg[0][1];
        cp_async16(dsth + tid * 16, gh + tid * 16);
        cp_async16(dsth + (tid + 256) * 16, gh + (tid + 256) * 16);
        cp_async16(dstl + tid * 16, gl + tid * 16);
        cp_async16(dstl + (tid + 256) * 16, gl + (tid + 256) * 16);
        CP_COMMIT();

        unsigned char* bufp = smem + SMEM_BUF0;
#pragma unroll
        for (int i = 0; i < 4; ++i) {
            int idx = tid + i * NTHREADS;
            store_a_split(bufp, idx >> 4, idx & 15, va[i]);
        }
        CP_WAIT0();
        __syncthreads();
    }

    // ---- main loop ----
    for (int c = 0; c < NCHUNK; ++c) {
        const int p = c & 1;
        const uint32_t buf = sb + SMEM_BUF0 + p * BUF_STRIDE;

        // issue loads for chunk c+1 (A -> regs, B -> other buffer via cp.async)
        if (c + 1 < NCHUNK) {
            const int cc = c + 1;
            const float* src;
            int ldx;
            if (cc < 2) { src = inp  + (size_t)row0 * NI + cc * KC; ldx = NI; }
            else        { src = prev + (size_t)row0 * NN + cc * KC; ldx = NN; }
#pragma unroll
            for (int i = 0; i < 4; ++i) {
                int idx = tid + i * NTHREADS;
                int r = idx >> 4, f4 = idx & 15;
                va[i] = *(const float4*)(src + (size_t)r * ldx + f4 * 4);
            }
            uint32_t dsth = sb + SMEM_BUF0 + (p ^ 1) * BUF_STRIDE + BH_OFF;
            uint32_t dstl = sb + SMEM_BUF0 + (p ^ 1) * BUF_STRIDE + BL_OFF;
            const unsigned char* gh = g_Bimg[cc][0];
            const unsigned char* gl = g_Bimg[cc][1];
            cp_async16(dsth + tid * 16, gh + tid * 16);
            cp_async16(dsth + (tid + 256) * 16, gh + (tid + 256) * 16);
            cp_async16(dstl + tid * 16, gl + tid * 16);
            cp_async16(dstl + (tid + 256) * 16, gl + (tid + 256) * 16);
            CP_COMMIT();
        }

        // compute chunk c from buffer p
#pragma unroll
        for (int ks = 0; ks < 4; ++ks) {
            uint32_t ah[2][4], alr[2][4];
#pragma unroll
            for (int mt = 0; mt < 2; ++mt) {
                int row = warpm * 32 + mt * 16 + (lane & 15);
                int kc2 = ks * 16 + (lane >> 4) * 8;
                uint32_t off = sw128((uint32_t)(row * 128 + kc2 * 2));
                ldm_x4(ah[mt],  buf + AH_OFF + off);
                ldm_x4(alr[mt], buf + AL_OFF + off);
            }
            uint32_t bh[4], blr[4];
            {
                int kr = ks * 16 + (lane & 15);
                int nc = warpn * 16 + (lane >> 4) * 8;
                uint32_t off = sw128((uint32_t)(kr * 128 + nc * 2));
                ldm_x4_t(bh,  buf + BH_OFF + off);
                ldm_x4_t(blr, buf + BL_OFF + off);
            }
#pragma unroll
            for (int mt = 0; mt < 2; ++mt)
#pragma unroll
                for (int nf = 0; nf < 2; ++nf) {
                    int s = nf * 2;
                    mma_bf16(acc[mt][nf], ah[mt],  bh[s],  bh[s + 1]);
                    mma_bf16(acc[mt][nf], ah[mt],  blr[s], blr[s + 1]);
                    mma_bf16(acc[mt][nf], alr[mt], bh[s],  bh[s + 1]);
                }
        }

        // store chunk c+1's A into the other buffer, wait for B, sync
        if (c + 1 < NCHUNK) {
            unsigned char* bufp = smem + SMEM_BUF0 + (p ^ 1) * BUF_STRIDE;
#pragma unroll
            for (int i = 0; i < 4; ++i) {
                int idx = tid + i * NTHREADS;
                store_a_split(bufp, idx >> 4, idx & 15, va[i]);
            }
            CP_WAIT0();
        }
        __syncthreads();
    }

    // ---- epilogue: bias + heterogeneous activation + store ----
#pragma unroll
    for (int mt = 0; mt < 2; ++mt)
#pragma unroll
        for (int nf = 0; nf < 2; ++nf) {
            int col = warpn * 16 + nf * 8 + (lane & 3) * 2;
            int rg  = row0 + warpm * 32 + mt * 16 + (lane >> 2);
            float b0 = sbias[col], b1 = sbias[col + 1];
            int   a0 = sact[col],  a1 = sact[col + 1];
            float2 o;
            o.x = activate(acc[mt][nf][0] + b0, a0);
            o.y = activate(acc[mt][nf][1] + b1, a1);
            *(float2*)(out + (size_t)rg * NO + col) = o;
            o.x = activate(acc[mt][nf][2] + b0, a0);
            o.y = activate(acc[mt][nf][3] + b1, a1);
            *(float2*)(out + (size_t)(rg + 8) * NO + col) = o;
        }
}

extern "C" void kernel_launch(void* const* d_in, const int* in_sizes, int n_in,
                              void* d_out, int out_size) {
    (void)in_sizes; (void)n_in; (void)out_size;
    const float* prev   = (const float*)d_in[0];  // [16384,1024]
    const float* inp    = (const float*)d_in[1];  // [16384,128]
    const float* W      = (const float*)d_in[2];  // [1024,1024]
    const float* biases = (const float*)d_in[3];  // [1024]
    const int*   act    = (const int*)d_in[4];    // [1024]
    float* out = (float*)d_out;                   // [16384,64]

    cudaFuncSetAttribute(nn_mma_kernel, cudaFuncAttributeMaxDynamicSharedMemorySize, SMEM_TOTAL);

    prep_kernel<<<(NN * NO + 255) / 256, 256>>>(W);
    nn_mma_kernel<<<BATCH / MT, NTHREADS, SMEM_TOTAL>>>(prev, inp, biases, act, out);
}

// round 5
// speedup vs baseline: 2.5607x; 1.1495x over previous
#include <cuda_runtime.h>
#include <cuda_bf16.h>
#include <cstdint>

// Problem constants
#define BATCH 16384
#define NN    1024
#define NI    128
#define NO    64
#define REFRACTORY 0.9f

// Tiling
#define MT       64             // batch rows per CTA
#define KC       64             // k per chunk
#define NCHUNK   (NN / KC)      // 16
#define NTHREADS 256            // 8 warps: 2 m-groups x 4 n-groups
#define STAGES   3

// ---- dynamic smem layout ----
// [0,256)  bias[64] f32   [256,512) act[64] i32
// [1024+)  ring of STAGES stages, 32KB each: A fp32 16KB | B packed fp32 16KB
#define SMEM_BIAS    0
#define SMEM_ACT     256
#define SMEM_BUF0    1024
#define A_OFF        0
#define B_OFF        16384
#define STAGE_STRIDE 32768
#define SMEM_TOTAL   (SMEM_BUF0 + STAGES * STAGE_STRIDE)   // 99328

// Pre-packed, tf32-rounded, refractory-folded weight slice.
// Layout: [chunk][warpn(4)][i(8)][lane(32)][4 floats] — each thread's 8
// float4 loads per chunk are lane-contiguous (conflict-free LDS.128).
// Value (i,lane,j): v = i*4+j; ks=v>>2; nf=(v>>1)&1; p=v&1;
//   k = chunk*64 + ks*8 + (lane&3) + p*4;  n = warpn*16 + nf*8 + (lane>>2)
__device__ __align__(16) float g_Bpack[NCHUNK][4][8][32][4];

__device__ __forceinline__ uint32_t smem_u32(const void* p) {
    uint32_t a;
    asm("{ .reg .u64 t; cvta.to.shared.u64 t, %1; cvt.u32.u64 %0, t; }" : "=r"(a) : "l"(p));
    return a;
}
__device__ __forceinline__ void ldm_x4(uint32_t* r, uint32_t addr) {
    asm volatile("ldmatrix.sync.aligned.m8n8.x4.shared.b16 {%0,%1,%2,%3}, [%4];"
                 : "=r"(r[0]), "=r"(r[1]), "=r"(r[2]), "=r"(r[3]) : "r"(addr));
}
__device__ __forceinline__ void mma_tf32(float* d, const uint32_t* a, uint32_t b0, uint32_t b1) {
    asm volatile(
        "mma.sync.aligned.m16n8k8.row.col.f32.tf32.tf32.f32 "
        "{%0,%1,%2,%3}, {%4,%5,%6,%7}, {%8,%9}, {%0,%1,%2,%3};"
        : "+f"(d[0]), "+f"(d[1]), "+f"(d[2]), "+f"(d[3])
        : "r"(a[0]), "r"(a[1]), "r"(a[2]), "r"(a[3]), "r"(b0), "r"(b1));
}
__device__ __forceinline__ uint32_t cvt_tf32(uint32_t x) {
    uint32_t d;
    asm("cvt.rna.tf32.f32 %0, %1;" : "=r"(d) : "f"(__uint_as_float(x)));
    return d;
}
__device__ __forceinline__ void cp_async16(uint32_t smem_addr, const void* gptr) {
    asm volatile("cp.async.cg.shared.global [%0], [%1], 16;"
                 :: "r"(smem_addr), "l"(gptr) : "memory");
}
#define CP_COMMIT() asm volatile("cp.async.commit_group;" ::: "memory")
#define CP_WAIT1()  asm volatile("cp.async.wait_group 1;" ::: "memory")

// A stage layout: 64 rows x 16 units(16B). Two 128B atoms per row.
// off = (u>>3)*8192 + row*128 + ((u&7)^(row&7))*16  — conflict-free for
// ldmatrix (8 rows, same unit) and for cp.async stores.
__device__ __forceinline__ uint32_t a_off(int row, int u) {
    return (uint32_t)((u >> 3) * 8192 + row * 128 + (((u & 7) ^ (row & 7)) << 4));
}

// ---------------- prep: round + fold + pack weight slice ----------------
__global__ void prep_kernel(const float* __restrict__ W) {
    int idx = blockIdx.x * blockDim.x + threadIdx.x;   // 0..65535
    if (idx >= NCHUNK * 4 * 8 * 32 * 4) return;
    int j     = idx & 3;
    int lane  = (idx >> 2) & 31;
    int i     = (idx >> 7) & 7;
    int warpn = (idx >> 10) & 3;
    int chunk = idx >> 12;
    int v  = i * 4 + j;
    int ks = v >> 2, nf = (v >> 1) & 1, p = v & 1;
    int k = chunk * 64 + ks * 8 + (lane & 3) + p * 4;
    int n = warpn * 16 + nf * 8 + (lane >> 2);
    float f = (k >= NI && k < NN - NO) ? REFRACTORY : 1.0f;
    float val = W[(size_t)k * NN + (NN - NO) + n] * f;
    ((float*)g_Bpack)[idx] = __uint_as_float(cvt_tf32(__float_as_uint(val)));
}

// ---------------- activation ----------------
__device__ __forceinline__ float activate(float x, int a) {
    if (a == 0) return fmaxf(x, 0.0f);
    if (a == 1) { float r; asm("tanh.approx.f32 %0, %1;" : "=f"(r) : "f"(x)); return r; }
    if (a == 2) {
        float e, r;
        asm("ex2.approx.f32 %0, %1;" : "=f"(e) : "f"(-1.4426950408889634f * x));
        asm("rcp.approx.f32 %0, %1;" : "=f"(r) : "f"(1.0f + e));
        return r;
    }
    return x;
}

// ---------------- main kernel ----------------
__global__ void __launch_bounds__(NTHREADS, 2)
nn_tf32_kernel(const float* __restrict__ prev,    // [B, N]
               const float* __restrict__ inp,     // [B, I]
               const float* __restrict__ biases,  // [N]
               const int*   __restrict__ act,     // [N]
               float* __restrict__ out)           // [B, O]
{
    extern __shared__ unsigned char smem[];
    const uint32_t sb = smem_u32(smem);
    const int tid   = threadIdx.x;
    const int lane  = tid & 31;
    const int wid   = tid >> 5;
    const int warpm = wid >> 2;   // 0..1 (32 rows each)
    const int warpn = wid & 3;    // 0..3 (16 cols each)
    const int row0  = blockIdx.x * MT;

    float* sbias = (float*)(smem + SMEM_BIAS);
    int*   sact  = (int*)(smem + SMEM_ACT);
    if (tid < NO) {
        sbias[tid] = biases[NN - NO + tid];
        sact[tid]  = act[NN - NO + tid];
    }

    // issue loads for chunk c into stage s
    auto issue = [&](int c, int s) {
        const uint32_t stage = sb + SMEM_BUF0 + s * STAGE_STRIDE;
        const float* src;
        int ldx;
        if (c < 2) { src = inp  + (size_t)row0 * NI + c * KC; ldx = NI; }
        else       { src = prev + (size_t)row0 * NN + c * KC; ldx = NN; }
#pragma unroll
        for (int i = 0; i < 4; ++i) {
            int g = tid + i * NTHREADS;          // 0..1023
            int row = g >> 4, u = g & 15;
            cp_async16(stage + A_OFF + a_off(row, u), src + (size_t)row * ldx + u * 4);
        }
        const float* bsrc = &g_Bpack[c][0][0][0][0];
#pragma unroll
        for (int i = 0; i < 4; ++i) {
            int g = tid + i * NTHREADS;
            cp_async16(stage + B_OFF + g * 16, bsrc + g * 4);
        }
    };

    float acc[2][2][4];
#pragma unroll
    for (int mt = 0; mt < 2; ++mt)
#pragma unroll
        for (int nf = 0; nf < 2; ++nf)
#pragma unroll
            for (int i = 0; i < 4; ++i) acc[mt][nf][i] = 0.0f;

    // prologue: stages 0,1
    issue(0, 0); CP_COMMIT();
    issue(1, 1); CP_COMMIT();

    const int r0w = warpm * 32 + (lane & 15);
    const int uhi = lane >> 4;

    for (int c = 0; c < NCHUNK; ++c) {
        const int s = c % STAGES;
        const uint32_t stage = sb + SMEM_BUF0 + s * STAGE_STRIDE;

        CP_WAIT1();            // groups 0..c complete
        __syncthreads();       // all warps past compute(c-1); stage (c+2)%3 free

        if (c + 2 < NCHUNK) issue(c + 2, (c + 2) % STAGES);
        CP_COMMIT();           // commit (possibly empty) to keep group count

        // B: 8 conflict-free LDS.128
        uint4 bq[8];
        const uint32_t bbase = stage + B_OFF + warpn * 4096 + lane * 16;
#pragma unroll
        for (int i = 0; i < 8; ++i)
            bq[i] = *(const uint4*)(smem + (bbase - sb) + i * 512);

#pragma unroll
        for (int ks = 0; ks < 8; ++ks) {
            uint32_t a[2][4];
#pragma unroll
            for (int mt = 0; mt < 2; ++mt) {
                int u = 2 * ks + uhi;
                ldm_x4(a[mt], stage + A_OFF + a_off(r0w + mt * 16, u));
#pragma unroll
                for (int q = 0; q < 4; ++q) a[mt][q] = cvt_tf32(a[mt][q]);
            }
            uint32_t b0h = bq[ks].x, b0l = bq[ks].y;   // nf=0: p=0,1
            uint32_t b1h = bq[ks].z, b1l = bq[ks].w;   // nf=1: p=0,1
#pragma unroll
            for (int mt = 0; mt < 2; ++mt) {
                mma_tf32(acc[mt][0], a[mt], b0h, b0l);
                mma_tf32(acc[mt][1], a[mt], b1h, b1l);
            }
        }
    }

    // ---- epilogue: bias + heterogeneous activation + store ----
#pragma unroll
    for (int mt = 0; mt < 2; ++mt)
#pragma unroll
        for (int nf = 0; nf < 2; ++nf) {
            int col = warpn * 16 + nf * 8 + (lane & 3) * 2;
            int rg  = row0 + warpm * 32 + mt * 16 + (lane >> 2);
            float b0 = sbias[col], b1 = sbias[col + 1];
            int   a0 = sact[col],  a1 = sact[col + 1];
            float2 o;
            o.x = activate(acc[mt][nf][0] + b0, a0);
            o.y = activate(acc[mt][nf][1] + b1, a1);
            *(float2*)(out + (size_t)rg * NO + col) = o;
            o.x = activate(acc[mt][nf][2] + b0, a0);
            o.y = activate(acc[mt][nf][3] + b1, a1);
            *(float2*)(out + (size_t)(rg + 8) * NO + col) = o;
        }
}

extern "C" void kernel_launch(void* const* d_in, const int* in_sizes, int n_in,
                              void* d_out, int out_size) {
    (void)in_sizes; (void)n_in; (void)out_size;
    const float* prev   = (const float*)d_in[0];  // [16384,1024]
    const float* inp    = (const float*)d_in[1];  // [16384,128]
    const float* W      = (const float*)d_in[2];  // [1024,1024]
    const float* biases = (const float*)d_in[3];  // [1024]
    const int*   act    = (const int*)d_in[4];    // [1024]
    float* out = (float*)d_out;                   // [16384,64]

    cudaFuncSetAttribute(nn_tf32_kernel, cudaFuncAttributeMaxDynamicSharedMemorySize, SMEM_TOTAL);

    prep_kernel<<<256, 256>>>(W);
    nn_tf32_kernel<<<BATCH / MT, NTHREADS, SMEM_TOTAL>>>(prev, inp, biases, act, out);
}